// round 6
// baseline (speedup 1.0000x reference)
#include <cuda_runtime.h>

#define N 4096

#define PED_SPEED  1.34f
#define K_GAIN     2.0f
#define ALPHA      10.66f
#define PED_RADIUS 0.3f
#define PED_MASS   60.0f
#define BETTA      0.71f
#define DT         0.4f
#define COST_A     1.0f
#define COST_B     1.0f
#define COST_E     1.0f
#define EPS        1e-8f

#define LOG2E      1.4426950408889634f
#define LOG2_ALPHA 3.4140815f

#define THREADS 1024
#define JHALF   (N / 2)

typedef unsigned long long u64;

__device__ __forceinline__ float fast_rsqrt(float x) {
    float y; asm("rsqrt.approx.ftz.f32 %0, %1;" : "=f"(y) : "f"(x)); return y;
}
__device__ __forceinline__ float fast_ex2(float x) {
    float y; asm("ex2.approx.ftz.f32 %0, %1;" : "=f"(y) : "f"(x)); return y;
}
__device__ __forceinline__ u64 f2_add(u64 a, u64 b) {
    u64 o; asm("add.rn.f32x2 %0, %1, %2;" : "=l"(o) : "l"(a), "l"(b)); return o;
}
__device__ __forceinline__ u64 f2_fma(u64 a, u64 b, u64 c) {
    u64 o; asm("fma.rn.f32x2 %0, %1, %2, %3;" : "=l"(o) : "l"(a), "l"(b), "l"(c)); return o;
}
__device__ __forceinline__ u64 pack2(float lo, float hi) {
    u64 o; asm("mov.b64 %0, {%1, %2};" : "=l"(o) : "f"(lo), "f"(hi)); return o;
}
__device__ __forceinline__ void unpack2(u64 v, float& lo, float& hi) {
    asm("mov.b64 {%0, %1}, %2;" : "=f"(lo), "=f"(hi) : "l"(v));
}

// Scalar pair (robot phase): f += (ALPHA*exp((2R-d)/B)/d)*(pi-pj), npj = -pj.
__device__ __forceinline__ void pair_acc_s(float xi, float yi, float npjx, float npjy,
                                           float& fx, float& fy, float cA, float cB2)
{
    const float dx = xi + npjx;
    const float dy = yi + npjy;
    const float d2 = fmaf(dx, dx, fmaf(dy, dy, EPS));
    const float rs = fast_rsqrt(d2);
    const float d  = d2 * rs;
    const float e  = fast_ex2(fmaf(d, cA, cB2));
    const float coef = e * rs;
    fx = fmaf(coef, dx, fx);
    fy = fmaf(coef, dy, fy);
}

// Dynamic shared: dupnegx[N], dupnegy[N] -- (-xj,-xj) / (-yj,-yj) packed b64.
extern __shared__ u64 dyn_smem[];

__global__ __launch_bounds__(THREADS, 1)
void fused_kernel(const float4* __restrict__ state,
                  const float*  __restrict__ cost_in,
                  const float2* __restrict__ goals,
                  const float*  __restrict__ robot_init_pose,
                  const float4* __restrict__ observed,
                  float4* __restrict__ out,
                  float*  __restrict__ cost_out,
                  int apb)                       // agents per block (even, <= 32)
{
    u64* __restrict__ dnx = dyn_smem;            // [N]
    u64* __restrict__ dny = dyn_smem + N;        // [N]

    __shared__ float4 fpart[32];                 // per-warp (fx1,fy1,fx2,fy2)
    __shared__ float2 rpart[32];                 // robot partials

    const int tid  = threadIdx.x;
    const int warp = tid >> 5;
    const int lane = tid & 31;

    // ---- Stage duplicated negated coordinates ----
    #pragma unroll
    for (int k = 0; k < N / THREADS; ++k) {
        const int j = tid + k * THREADS;
        const float4 s = state[j];
        dnx[j] = pack2(-s.x, -s.x);
        dny[j] = pack2(-s.y, -s.y);
    }
    __syncthreads();

    const float cA  = -(1.0f / BETTA) * LOG2E;
    const float cB2 = (2.0f * PED_RADIUS / BETTA) * LOG2E + LOG2_ALPHA;

    // ---- Phase 1: robot (agent 0) repulsion, all warps, scalar ----
    {
        float n0x, n0y, dum;
        unpack2(dnx[0], n0x, dum);
        unpack2(dny[0], n0y, dum);
        const float p0x = -n0x, p0y = -n0y;
        float rfx = 0.0f, rfy = 0.0f;
        #pragma unroll
        for (int k = 0; k < N / THREADS; ++k) {
            const int j = tid + k * THREADS;
            float nx, ny;
            unpack2(dnx[j], nx, dum);
            unpack2(dny[j], ny, dum);
            pair_acc_s(p0x, p0y, nx, ny, rfx, rfy, cA, cB2);
        }
        #pragma unroll
        for (int off = 16; off > 0; off >>= 1) {
            rfx += __shfl_xor_sync(0xffffffffu, rfx, off);
            rfy += __shfl_xor_sync(0xffffffffu, rfy, off);
        }
        if (lane == 0) rpart[warp] = make_float2(rfx, rfy);
    }

    // ---- Phase 2: each warp = (agent pair, j-half). 2 pairs per iteration ----
    if (warp < apb) {
        const int pidx = warp >> 1;               // agent pair index
        const int half = warp & 1;                // j half
        int i1 = blockIdx.x * apb + 2 * pidx;
        int i2 = i1 + 1;
        if (i1 > N - 1) i1 = N - 1;               // clamp (guarded at write)
        if (i2 > N - 1) i2 = N - 1;

        float n1x, n1y, n2x, n2y, dum;
        unpack2(dnx[i1], n1x, dum);
        unpack2(dny[i1], n1y, dum);
        unpack2(dnx[i2], n2x, dum);
        unpack2(dny[i2], n2y, dum);
        const u64 xi12 = pack2(-n1x, -n2x);       // loop-invariant packs
        const u64 yi12 = pack2(-n1y, -n2y);
        const u64 eps2 = pack2(EPS, EPS);

        float fx1 = 0.0f, fy1 = 0.0f, fx2 = 0.0f, fy2 = 0.0f;
        const int jbase = half * JHALF + lane;
        #pragma unroll 8
        for (int k = 0; k < JHALF / 32; ++k) {    // 64 iterations
            const int j = jbase + k * 32;
            const u64 dx2 = f2_add(xi12, dnx[j]); // (x_i1-x_j, x_i2-x_j)
            const u64 dy2 = f2_add(yi12, dny[j]);
            const u64 d22 = f2_fma(dx2, dx2, f2_fma(dy2, dy2, eps2));

            float d2a, d2b, dxa, dxb, dya, dyb;
            unpack2(d22, d2a, d2b);
            unpack2(dx2, dxa, dxb);
            unpack2(dy2, dya, dyb);

            const float rsa = fast_rsqrt(d2a);
            const float rsb = fast_rsqrt(d2b);
            const float da  = d2a * rsa;
            const float db  = d2b * rsb;
            const float ea  = fast_ex2(fmaf(da, cA, cB2));
            const float eb  = fast_ex2(fmaf(db, cA, cB2));
            const float ca  = ea * rsa;
            const float cb  = eb * rsb;
            fx1 = fmaf(ca, dxa, fx1);
            fy1 = fmaf(ca, dya, fy1);
            fx2 = fmaf(cb, dxb, fx2);
            fy2 = fmaf(cb, dyb, fy2);
        }
        #pragma unroll
        for (int off = 16; off > 0; off >>= 1) {
            fx1 += __shfl_xor_sync(0xffffffffu, fx1, off);
            fy1 += __shfl_xor_sync(0xffffffffu, fy1, off);
            fx2 += __shfl_xor_sync(0xffffffffu, fx2, off);
            fy2 += __shfl_xor_sync(0xffffffffu, fy2, off);
        }
        if (lane == 0) fpart[warp] = make_float4(fx1, fy1, fx2, fy2);
    }

    __syncthreads();

    // ---- Epilogue: one thread per agent ----
    if (tid < apb) {
        const int ia = blockIdx.x * apb + tid;
        if (ia < N) {
            // robot total repulsion (deterministic order)
            float Rfx = 0.0f, Rfy = 0.0f;
            #pragma unroll
            for (int w = 0; w < 32; ++w) { Rfx += rpart[w].x; Rfy += rpart[w].y; }

            // robot new pose
            const float4 s0 = state[0];
            const float2 g0 = goals[0];
            float r0x, r0y;
            {
                const float tgx = g0.x - s0.x;
                const float tgy = g0.y - s0.y;
                const float inv_gd = fast_rsqrt(fmaf(tgx, tgx, fmaf(tgy, tgy, EPS)));
                const float Fx = Rfx + K_GAIN * PED_MASS * (PED_SPEED * tgx * inv_gd - s0.z);
                const float Fy = Rfy + K_GAIN * PED_MASS * (PED_SPEED * tgy * inv_gd - s0.w);
                float vnx = fmaf(Fx, DT / PED_MASS, s0.z);
                float vny = fmaf(Fy, DT / PED_MASS, s0.w);
                const float spd = sqrtf(fmaf(vnx, vnx, fmaf(vny, vny, EPS)));
                const float sc = fminf(1.0f, PED_SPEED / spd);
                vnx *= sc; vny *= sc;
                r0x = fmaf(vnx, DT, s0.x);
                r0y = fmaf(vny, DT, s0.y);
            }

            // combine the two j-half warps for this agent
            const int pidx = tid >> 1;
            const int sel  = tid & 1;
            const float4 h0 = fpart[2 * pidx + 0];
            const float4 h1 = fpart[2 * pidx + 1];
            const float afx = sel ? (h0.z + h1.z) : (h0.x + h1.x);
            const float afy = sel ? (h0.w + h1.w) : (h0.y + h1.y);

            const float4 s = state[ia];
            const float2 g = goals[ia];
            const float tgx = g.x - s.x;
            const float tgy = g.y - s.y;
            const float inv_gd = fast_rsqrt(fmaf(tgx, tgx, fmaf(tgy, tgy, EPS)));
            const float Fx = afx + K_GAIN * PED_MASS * (PED_SPEED * tgx * inv_gd - s.z);
            const float Fy = afy + K_GAIN * PED_MASS * (PED_SPEED * tgy * inv_gd - s.w);

            float vnx = fmaf(Fx, DT / PED_MASS, s.z);
            float vny = fmaf(Fy, DT / PED_MASS, s.w);
            const float spd = sqrtf(fmaf(vnx, vnx, fmaf(vny, vny, EPS)));
            const float sc = fminf(1.0f, PED_SPEED / spd);
            vnx *= sc; vny *= sc;
            const float pnx = fmaf(vnx, DT, s.x);
            const float pny = fmaf(vny, DT, s.y);

            out[ia] = make_float4(pnx, pny, vnx, vny);

            // cost
            const float ripx = robot_init_pose[0];
            const float ripy = robot_init_pose[1];
            const float gvx = g0.x - ripx;
            const float gvy = g0.y - ripy;
            const float gnorm = sqrtf(gvx * gvx + gvy * gvy) + EPS;
            const float pg = ((r0x - ripx) * gvx + (r0y - ripy) * gvy) / gnorm;

            const float ddx = pnx - r0x;
            const float ddy = pny - r0y;
            const float dist = sqrtf(fmaf(ddx, ddx, fmaf(ddy, ddy, EPS)));
            const float blame = COST_B * fast_ex2(-dist * (LOG2E / COST_E));

            const float4 obs = observed[ia];
            const float ox = pnx - obs.x;
            const float oy = pny - obs.y;
            const float dev = fmaf(ox, ox, oy * oy);

            cost_out[ia] = cost_in[ia] + (-COST_A * pg + blame + dev);
        }
    }
}

extern "C" void kernel_launch(void* const* d_in, const int* in_sizes, int n_in,
                              void* d_out, int out_size)
{
    const float4* state    = (const float4*)d_in[0];
    const float*  cost_in  = (const float*) d_in[1];
    const float2* goals    = (const float2*)d_in[2];
    const float*  rip      = (const float*) d_in[3];
    const float4* observed = (const float4*)d_in[4];

    float4* out_state = (float4*)d_out;
    float*  cost_out  = (float*)d_out + (size_t)N * 4;

    int nsm = 0;
    if (cudaDeviceGetAttribute(&nsm, cudaDevAttrMultiProcessorCount, 0) != cudaSuccess
        || nsm <= 0) nsm = 148;
    if (nsm > N) nsm = N;
    int apb = (N + nsm - 1) / nsm;
    apb = (apb + 1) & ~1;                        // even (agent pairs)
    if (apb > 32) apb = 32;

    const size_t shmem = 2u * N * sizeof(unsigned long long);  // 64 KB
    cudaFuncSetAttribute(fused_kernel, cudaFuncAttributeMaxDynamicSharedMemorySize,
                         (int)shmem);

    fused_kernel<<<nsm, THREADS, shmem>>>(state, cost_in, goals, rip, observed,
                                          out_state, cost_out, apb);
}

// round 8
// speedup vs baseline: 1.0194x; 1.0194x over previous
#include <cuda_runtime.h>

#define N 4096

#define PED_SPEED  1.34f
#define K_GAIN     2.0f
#define ALPHA      10.66f
#define PED_RADIUS 0.3f
#define PED_MASS   60.0f
#define BETTA      0.71f
#define DT         0.4f
#define COST_A     1.0f
#define COST_B     1.0f
#define COST_E     1.0f
#define EPS        1e-8f

#define LOG2E      1.4426950408889634f
#define LOG2_ALPHA 3.4140815f

#define THREADS 512
#define WPB     16
#define J4ALL   (N / 2)        // 2048 float4 entries (2 agents each)
#define J4ITERS (J4ALL / 32)   // 64 inner iterations per warp, 2 pairs each

__device__ __forceinline__ float fast_rsqrt(float x) {
    float y; asm("rsqrt.approx.ftz.f32 %0, %1;" : "=f"(y) : "f"(x)); return y;
}
__device__ __forceinline__ float fast_ex2(float x) {
    float y; asm("ex2.approx.ftz.f32 %0, %1;" : "=f"(y) : "f"(x)); return y;
}

// One pair: f += (ALPHA*exp((2R-d)/B)/d) * (pi - pj). i==j gives exactly 0.
__device__ __forceinline__ void pair_acc(float xi, float yi, float pjx, float pjy,
                                         float& fx, float& fy, float cA, float cB2)
{
    const float dx = xi - pjx;
    const float dy = yi - pjy;
    const float d2 = fmaf(dx, dx, fmaf(dy, dy, EPS));
    const float rs = fast_rsqrt(d2);             // 1/d   (MUFU.RSQ)
    const float d  = d2 * rs;                    // d
    const float e  = fast_ex2(fmaf(d, cA, cB2)); // ALPHA * exp((2R-d)/B)  (MUFU.EX2)
    const float coef = e * rs;
    fx = fmaf(coef, dx, fx);
    fy = fmaf(coef, dy, fy);
}

// Two 512-thread blocks per SM (64-warp occupancy), 64-reg budget preserved.
// One warp per agent, full j sweep from shared positions.
__global__ __launch_bounds__(THREADS, 2)
void fused_kernel(const float4* __restrict__ state,
                  const float*  __restrict__ cost_in,
                  const float2* __restrict__ goals,
                  const float*  __restrict__ robot_init_pose,
                  const float4* __restrict__ observed,
                  float4* __restrict__ out,
                  float*  __restrict__ cost_out,
                  int apb)                        // agents per block (~14)
{
    __shared__ float2 spos[N];       // (x, y) per agent, 32 KB
    __shared__ float2 fpart[WPB];    // per-warp agent forces
    __shared__ float2 rpart[WPB];    // per-warp robot partials

    const int tid  = threadIdx.x;
    const int warp = tid >> 5;
    const int lane = tid & 31;

    // ---- Stage positions into shared (8 iters) ----
    #pragma unroll
    for (int k = 0; k < N / THREADS; ++k) {
        const int j = tid + k * THREADS;
        const float4 s = state[j];
        spos[j] = make_float2(s.x, s.y);
    }
    __syncthreads();

    const float cA  = -(1.0f / BETTA) * LOG2E;
    const float cB2 = (2.0f * PED_RADIUS / BETTA) * LOG2E + LOG2_ALPHA;

    const float4* __restrict__ spos4 = (const float4*)spos;  // 2 agents per entry

    // ---- Phase 1: robot (agent 0) repulsion, all 16 warps (8 pairs/thread) ----
    {
        const float2 p0 = spos[0];
        float rfx = 0.0f, rfy = 0.0f;
        #pragma unroll
        for (int k = 0; k < J4ALL / THREADS; ++k) {   // 4 iterations x 2 pairs
            const float4 p = spos4[tid + k * THREADS];
            pair_acc(p0.x, p0.y, p.x, p.y, rfx, rfy, cA, cB2);
            pair_acc(p0.x, p0.y, p.z, p.w, rfx, rfy, cA, cB2);
        }
        #pragma unroll
        for (int off = 16; off > 0; off >>= 1) {
            rfx += __shfl_xor_sync(0xffffffffu, rfx, off);
            rfy += __shfl_xor_sync(0xffffffffu, rfy, off);
        }
        if (lane == 0) rpart[warp] = make_float2(rfx, rfy);
    }

    // ---- Phase 2: one warp per agent, full j sweep (64 iters x 2 pairs) ----
    const int i = blockIdx.x * apb + warp;
    if (warp < apb && i < N) {
        const float2 pi = spos[i];
        const float xi = pi.x, yi = pi.y;

        float fx = 0.0f, fy = 0.0f;
        #pragma unroll 8
        for (int k = 0; k < J4ITERS; ++k) {
            const float4 p = spos4[lane + k * 32];
            pair_acc(xi, yi, p.x, p.y, fx, fy, cA, cB2);
            pair_acc(xi, yi, p.z, p.w, fx, fy, cA, cB2);
        }
        #pragma unroll
        for (int off = 16; off > 0; off >>= 1) {
            fx += __shfl_xor_sync(0xffffffffu, fx, off);
            fy += __shfl_xor_sync(0xffffffffu, fy, off);
        }
        if (lane == 0) fpart[warp] = make_float2(fx, fy);
    }

    __syncthreads();

    // ---- Epilogue: one thread per agent ----
    if (tid < apb) {
        const int ia = blockIdx.x * apb + tid;
        if (ia < N) {
            // robot total repulsion (deterministic in-block order)
            float Rfx = 0.0f, Rfy = 0.0f;
            #pragma unroll
            for (int w = 0; w < WPB; ++w) { Rfx += rpart[w].x; Rfy += rpart[w].y; }

            // robot new pose
            const float4 s0 = state[0];
            const float2 g0 = goals[0];
            float r0x, r0y;
            {
                const float tgx = g0.x - s0.x;
                const float tgy = g0.y - s0.y;
                const float inv_gd = fast_rsqrt(fmaf(tgx, tgx, fmaf(tgy, tgy, EPS)));
                const float Fx = Rfx + K_GAIN * PED_MASS * (PED_SPEED * tgx * inv_gd - s0.z);
                const float Fy = Rfy + K_GAIN * PED_MASS * (PED_SPEED * tgy * inv_gd - s0.w);
                float vnx = fmaf(Fx, DT / PED_MASS, s0.z);
                float vny = fmaf(Fy, DT / PED_MASS, s0.w);
                const float spd = sqrtf(fmaf(vnx, vnx, fmaf(vny, vny, EPS)));
                const float sc = fminf(1.0f, PED_SPEED / spd);
                vnx *= sc; vny *= sc;
                r0x = fmaf(vnx, DT, s0.x);
                r0y = fmaf(vny, DT, s0.y);
            }

            // this agent: attraction + propagation
            const float afx = fpart[tid].x;
            const float afy = fpart[tid].y;

            const float4 s = state[ia];
            const float2 g = goals[ia];
            const float tgx = g.x - s.x;
            const float tgy = g.y - s.y;
            const float inv_gd = fast_rsqrt(fmaf(tgx, tgx, fmaf(tgy, tgy, EPS)));
            const float Fx = afx + K_GAIN * PED_MASS * (PED_SPEED * tgx * inv_gd - s.z);
            const float Fy = afy + K_GAIN * PED_MASS * (PED_SPEED * tgy * inv_gd - s.w);

            float vnx = fmaf(Fx, DT / PED_MASS, s.z);
            float vny = fmaf(Fy, DT / PED_MASS, s.w);
            const float spd = sqrtf(fmaf(vnx, vnx, fmaf(vny, vny, EPS)));
            const float sc = fminf(1.0f, PED_SPEED / spd);
            vnx *= sc; vny *= sc;
            const float pnx = fmaf(vnx, DT, s.x);
            const float pny = fmaf(vny, DT, s.y);

            out[ia] = make_float4(pnx, pny, vnx, vny);

            // cost
            const float ripx = robot_init_pose[0];
            const float ripy = robot_init_pose[1];
            const float gvx = g0.x - ripx;
            const float gvy = g0.y - ripy;
            const float gnorm = sqrtf(gvx * gvx + gvy * gvy) + EPS;
            const float pg = ((r0x - ripx) * gvx + (r0y - ripy) * gvy) / gnorm;

            const float ddx = pnx - r0x;
            const float ddy = pny - r0y;
            const float dist = sqrtf(fmaf(ddx, ddx, fmaf(ddy, ddy, EPS)));
            const float blame = COST_B * fast_ex2(-dist * (LOG2E / COST_E));

            const float4 obs = observed[ia];
            const float ox = pnx - obs.x;
            const float oy = pny - obs.y;
            const float dev = fmaf(ox, ox, oy * oy);

            cost_out[ia] = cost_in[ia] + (-COST_A * pg + blame + dev);
        }
    }
}

extern "C" void kernel_launch(void* const* d_in, const int* in_sizes, int n_in,
                              void* d_out, int out_size)
{
    const float4* state    = (const float4*)d_in[0];
    const float*  cost_in  = (const float*) d_in[1];
    const float2* goals    = (const float2*)d_in[2];
    const float*  rip      = (const float*) d_in[3];
    const float4* observed = (const float4*)d_in[4];

    float4* out_state = (float4*)d_out;
    float*  cost_out  = (float*)d_out + (size_t)N * 4;

    // Two blocks per SM, one wave (host code runs at graph-capture time only).
    int nsm = 0;
    if (cudaDeviceGetAttribute(&nsm, cudaDevAttrMultiProcessorCount, 0) != cudaSuccess
        || nsm <= 0) nsm = 148;
    int nblk_target = 2 * nsm;                  // 304 on GB300
    if (nblk_target > N) nblk_target = N;
    int apb = (N + nblk_target - 1) / nblk_target;   // 14
    if (apb > WPB) apb = WPB;
    const int nblk = (N + apb - 1) / apb;            // 293 -> no fully-idle blocks

    fused_kernel<<<nblk, THREADS>>>(state, cost_in, goals, rip, observed,
                                    out_state, cost_out, apb);
}

// round 9
// speedup vs baseline: 1.0396x; 1.0198x over previous
#include <cuda_runtime.h>

#define N 4096

#define PED_SPEED  1.34f
#define K_GAIN     2.0f
#define ALPHA      10.66f
#define PED_RADIUS 0.3f
#define PED_MASS   60.0f
#define BETTA      0.71f
#define DT         0.4f
#define COST_A     1.0f
#define COST_B     1.0f
#define COST_E     1.0f
#define EPS        1e-8f

#define LOG2E      1.4426950408889634f
#define LOG2_ALPHA 3.4140815f

#define THREADS 1024
#define WPB     32
#define APB     28                 // agents per block (even), grid = 147
#define JHALF   (N / 2)            // 2048 j per half
#define J4HALF  (JHALF / 2)        // 1024 float4 per half
#define J4ITERS (J4HALF / 32)      // 32 inner iterations, 2 j x 2 agents = 4 pairs

__device__ __forceinline__ float fast_rsqrt(float x) {
    float y; asm("rsqrt.approx.ftz.f32 %0, %1;" : "=f"(y) : "f"(x)); return y;
}
__device__ __forceinline__ float fast_ex2(float x) {
    float y; asm("ex2.approx.ftz.f32 %0, %1;" : "=f"(y) : "f"(x)); return y;
}

// One pair: f += (ALPHA*exp((2R-d)/B)/d) * (pi - pj). i==j gives exactly 0.
__device__ __forceinline__ void pair_acc(float xi, float yi, float pjx, float pjy,
                                         float& fx, float& fy, float cA, float cB2)
{
    const float dx = xi - pjx;
    const float dy = yi - pjy;
    const float d2 = fmaf(dx, dx, fmaf(dy, dy, EPS));
    const float rs = fast_rsqrt(d2);             // MUFU.RSQ
    const float d  = d2 * rs;
    const float e  = fast_ex2(fmaf(d, cA, cB2)); // MUFU.EX2 (ALPHA folded in)
    const float coef = e * rs;
    fx = fmaf(coef, dx, fx);
    fy = fmaf(coef, dy, fy);
}

// Single 1024-thread block per SM (R5 operating point, 64-reg budget).
// Each warp = (agent pair, j half): 4 independent pair chains per LDS.128,
// doubling ILP at identical occupancy.
__global__ __launch_bounds__(THREADS, 1)
void fused_kernel(const float4* __restrict__ state,
                  const float*  __restrict__ cost_in,
                  const float2* __restrict__ goals,
                  const float*  __restrict__ robot_init_pose,
                  const float4* __restrict__ observed,
                  float4* __restrict__ out,
                  float*  __restrict__ cost_out)
{
    __shared__ float2 spos[N];       // (x, y) per agent, 32 KB
    __shared__ float4 fpart[WPB];    // per-warp (fx_i1, fy_i1, fx_i2, fy_i2)
    __shared__ float2 rpart[WPB];    // per-warp robot partials

    const int tid  = threadIdx.x;
    const int warp = tid >> 5;
    const int lane = tid & 31;

    // ---- Stage positions into shared ----
    #pragma unroll
    for (int k = 0; k < N / THREADS; ++k) {
        const int j = tid + k * THREADS;
        const float4 s = state[j];
        spos[j] = make_float2(s.x, s.y);
    }
    __syncthreads();

    const float cA  = -(1.0f / BETTA) * LOG2E;
    const float cB2 = (2.0f * PED_RADIUS / BETTA) * LOG2E + LOG2_ALPHA;

    const float4* __restrict__ spos4 = (const float4*)spos;  // 2 agents per entry

    // ---- Phase 1: robot (agent 0) repulsion, all warps (4 pairs/thread) ----
    {
        const float2 p0 = spos[0];
        float rfx = 0.0f, rfy = 0.0f;
        #pragma unroll
        for (int k = 0; k < (N / 2) / THREADS; ++k) {   // 2 iters x 2 pairs
            const float4 p = spos4[tid + k * THREADS];
            pair_acc(p0.x, p0.y, p.x, p.y, rfx, rfy, cA, cB2);
            pair_acc(p0.x, p0.y, p.z, p.w, rfx, rfy, cA, cB2);
        }
        #pragma unroll
        for (int off = 16; off > 0; off >>= 1) {
            rfx += __shfl_xor_sync(0xffffffffu, rfx, off);
            rfy += __shfl_xor_sync(0xffffffffu, rfy, off);
        }
        if (lane == 0) rpart[warp] = make_float2(rfx, rfy);
    }

    // ---- Phase 2: warp = (agent pair, j-half); 4 pairs per iteration ----
    if (warp < APB) {
        const int pidx = warp >> 1;                 // 0..13
        const int half = warp & 1;                  // 0..1
        int i1 = blockIdx.x * APB + 2 * pidx;
        int i2 = i1 + 1;
        if (i1 > N - 1) i1 = N - 1;                 // clamp; writes guarded later
        if (i2 > N - 1) i2 = N - 1;

        const float2 p1 = spos[i1];
        const float2 p2 = spos[i2];
        const float x1 = p1.x, y1 = p1.y;
        const float x2 = p2.x, y2 = p2.y;

        float fx1 = 0.0f, fy1 = 0.0f, fx2 = 0.0f, fy2 = 0.0f;
        const int jbase = half * J4HALF + lane;     // float4 index
        #pragma unroll 4
        for (int k = 0; k < J4ITERS; ++k) {         // 32 iterations
            const float4 p = spos4[jbase + k * 32];
            pair_acc(x1, y1, p.x, p.y, fx1, fy1, cA, cB2);
            pair_acc(x2, y2, p.x, p.y, fx2, fy2, cA, cB2);
            pair_acc(x1, y1, p.z, p.w, fx1, fy1, cA, cB2);
            pair_acc(x2, y2, p.z, p.w, fx2, fy2, cA, cB2);
        }
        #pragma unroll
        for (int off = 16; off > 0; off >>= 1) {
            fx1 += __shfl_xor_sync(0xffffffffu, fx1, off);
            fy1 += __shfl_xor_sync(0xffffffffu, fy1, off);
            fx2 += __shfl_xor_sync(0xffffffffu, fx2, off);
            fy2 += __shfl_xor_sync(0xffffffffu, fy2, off);
        }
        if (lane == 0) fpart[warp] = make_float4(fx1, fy1, fx2, fy2);
    }

    __syncthreads();

    // ---- Epilogue: one thread per agent ----
    if (tid < APB) {
        const int ia = blockIdx.x * APB + tid;
        if (ia < N) {
            // robot total repulsion (deterministic in-block order)
            float Rfx = 0.0f, Rfy = 0.0f;
            #pragma unroll
            for (int w = 0; w < WPB; ++w) { Rfx += rpart[w].x; Rfy += rpart[w].y; }

            // robot new pose
            const float4 s0 = state[0];
            const float2 g0 = goals[0];
            float r0x, r0y;
            {
                const float tgx = g0.x - s0.x;
                const float tgy = g0.y - s0.y;
                const float inv_gd = fast_rsqrt(fmaf(tgx, tgx, fmaf(tgy, tgy, EPS)));
                const float Fx = Rfx + K_GAIN * PED_MASS * (PED_SPEED * tgx * inv_gd - s0.z);
                const float Fy = Rfy + K_GAIN * PED_MASS * (PED_SPEED * tgy * inv_gd - s0.w);
                float vnx = fmaf(Fx, DT / PED_MASS, s0.z);
                float vny = fmaf(Fy, DT / PED_MASS, s0.w);
                const float spd = sqrtf(fmaf(vnx, vnx, fmaf(vny, vny, EPS)));
                const float sc = fminf(1.0f, PED_SPEED / spd);
                vnx *= sc; vny *= sc;
                r0x = fmaf(vnx, DT, s0.x);
                r0y = fmaf(vny, DT, s0.y);
            }

            // combine the two j-half warps for this agent
            const int pidx = tid >> 1;
            const int sel  = tid & 1;
            const float4 h0 = fpart[2 * pidx + 0];
            const float4 h1 = fpart[2 * pidx + 1];
            const float afx = sel ? (h0.z + h1.z) : (h0.x + h1.x);
            const float afy = sel ? (h0.w + h1.w) : (h0.y + h1.y);

            const float4 s = state[ia];
            const float2 g = goals[ia];
            const float tgx = g.x - s.x;
            const float tgy = g.y - s.y;
            const float inv_gd = fast_rsqrt(fmaf(tgx, tgx, fmaf(tgy, tgy, EPS)));
            const float Fx = afx + K_GAIN * PED_MASS * (PED_SPEED * tgx * inv_gd - s.z);
            const float Fy = afy + K_GAIN * PED_MASS * (PED_SPEED * tgy * inv_gd - s.w);

            float vnx = fmaf(Fx, DT / PED_MASS, s.z);
            float vny = fmaf(Fy, DT / PED_MASS, s.w);
            const float spd = sqrtf(fmaf(vnx, vnx, fmaf(vny, vny, EPS)));
            const float sc = fminf(1.0f, PED_SPEED / spd);
            vnx *= sc; vny *= sc;
            const float pnx = fmaf(vnx, DT, s.x);
            const float pny = fmaf(vny, DT, s.y);

            out[ia] = make_float4(pnx, pny, vnx, vny);

            // cost
            const float ripx = robot_init_pose[0];
            const float ripy = robot_init_pose[1];
            const float gvx = g0.x - ripx;
            const float gvy = g0.y - ripy;
            const float gnorm = sqrtf(gvx * gvx + gvy * gvy) + EPS;
            const float pg = ((r0x - ripx) * gvx + (r0y - ripy) * gvy) / gnorm;

            const float ddx = pnx - r0x;
            const float ddy = pny - r0y;
            const float dist = sqrtf(fmaf(ddx, ddx, fmaf(ddy, ddy, EPS)));
            const float blame = COST_B * fast_ex2(-dist * (LOG2E / COST_E));

            const float4 obs = observed[ia];
            const float ox = pnx - obs.x;
            const float oy = pny - obs.y;
            const float dev = fmaf(ox, ox, oy * oy);

            cost_out[ia] = cost_in[ia] + (-COST_A * pg + blame + dev);
        }
    }
}

extern "C" void kernel_launch(void* const* d_in, const int* in_sizes, int n_in,
                              void* d_out, int out_size)
{
    const float4* state    = (const float4*)d_in[0];
    const float*  cost_in  = (const float*) d_in[1];
    const float2* goals    = (const float2*)d_in[2];
    const float*  rip      = (const float*) d_in[3];
    const float4* observed = (const float4*)d_in[4];

    float4* out_state = (float4*)d_out;
    float*  cost_out  = (float*)d_out + (size_t)N * 4;

    const int nblk = (N + APB - 1) / APB;   // 147 blocks, single wave
    fused_kernel<<<nblk, THREADS>>>(state, cost_in, goals, rip, observed,
                                    out_state, cost_out);
}